// round 3
// baseline (speedup 1.0000x reference)
#include <cuda_runtime.h>

#define N_NODES  50000
#define N_REL    16
#define HID      128
#define N_LAYERS 3
#define N_EDGES  1600000

// ---------------- device scratch (no cudaMalloc allowed) ----------------
__device__ __align__(16) float g_xprime[(size_t)N_NODES * N_REL * HID]; // 409.6 MB
__device__ __align__(16) float g_bufA[(size_t)N_NODES * HID];           // 25.6 MB
__device__ __align__(16) float g_bufB[(size_t)N_NODES * HID];           // 25.6 MB
__device__ __align__(16) float g_invc[N_NODES * N_REL];
__device__ int g_cnt [N_NODES * N_REL];
__device__ int g_srcOff[N_EDGES];   // src*R*HID + et*HID, or -1 if invalid
__device__ int g_segid [N_EDGES];   // tgt*R + et
__device__ int g_tgt   [N_EDGES];

// ---------------- edge prep ----------------
__global__ void zero_cnt_kernel() {
    int i = blockIdx.x * blockDim.x + threadIdx.x;
    if (i < N_NODES * N_REL) g_cnt[i] = 0;
}

// edge_index / edge_type arrive as int32 (harness downcasts int64 inputs;
// only float32/int32/bf16 exist per the stub contract).
__global__ void prep_edges_kernel(const int* __restrict__ edge_index,
                                  const int* __restrict__ edge_type) {
    int e = blockIdx.x * blockDim.x + threadIdx.x;
    if (e >= N_EDGES) return;
    int s = edge_index[e];
    int t = edge_index[N_EDGES + e];
    int r = edge_type[e];
    // Fault-proof guard: if any index is out of range (dtype mismatch, etc.),
    // mark the edge invalid instead of corrupting memory / trapping.
    if ((unsigned)s >= N_NODES || (unsigned)t >= N_NODES || (unsigned)r >= N_REL) {
        g_srcOff[e] = -1;
        g_segid[e]  = 0;
        g_tgt[e]    = 0;
        return;
    }
    g_srcOff[e] = s * (N_REL * HID) + r * HID;
    g_segid[e]  = t * N_REL + r;
    g_tgt[e]    = t;
    atomicAdd(&g_cnt[t * N_REL + r], 1);
}

__global__ void make_invc_kernel() {
    int i = blockIdx.x * blockDim.x + threadIdx.x;
    if (i < N_NODES * N_REL) {
        int c = g_cnt[i];
        g_invc[i] = 1.0f / (float)(c > 0 ? c : 1);
    }
}

// ---------------- SGEMM: C[n, z*HID + j] (+= bias) = act(A[n,:]) @ B_z ----------------
// A: [Nrows, 128] row-major. Bbase + z*128*128: [128,128] row-major.
// Tile 128x128, BK=16, 256 threads, 8x8 micro-tile per thread.
__global__ __launch_bounds__(256) void sgemm_rgcn(
    const float* __restrict__ A, const float* __restrict__ Bbase,
    float* __restrict__ Cbase, int ldc, const float* __restrict__ bias,
    int relu, int Nrows)
{
    const float* B = Bbase + (size_t)blockIdx.z * HID * HID;
    float* C = Cbase + (size_t)blockIdx.z * HID;

    __shared__ __align__(16) float As[16][128];   // [k][m]
    __shared__ __align__(16) float Bs[16][128];   // [k][n]

    const int tid = threadIdx.x;
    const int rowBase = blockIdx.x * 128;
    const int tx = tid & 15;
    const int ty = tid >> 4;
    const int cRow = ty * 8;
    const int cCol = tx * 8;

    float acc[8][8];
    #pragma unroll
    for (int i = 0; i < 8; i++)
        #pragma unroll
        for (int j = 0; j < 8; j++) acc[i][j] = 0.0f;

    for (int k0 = 0; k0 < HID; k0 += 16) {
        // load A tile (128 x 16), store transposed into As[k][m]
        #pragma unroll
        for (int i = 0; i < 2; i++) {
            int idx = tid + i * 256;          // 0..511
            int m   = idx >> 2;               // 0..127
            int kq  = (idx & 3) << 2;         // 0,4,8,12
            int gr  = rowBase + m;
            float4 v = make_float4(0.f, 0.f, 0.f, 0.f);
            if (gr < Nrows)
                v = *(const float4*)(A + (size_t)gr * HID + k0 + kq);
            if (relu) {
                v.x = fmaxf(v.x, 0.f); v.y = fmaxf(v.y, 0.f);
                v.z = fmaxf(v.z, 0.f); v.w = fmaxf(v.w, 0.f);
            }
            As[kq + 0][m] = v.x; As[kq + 1][m] = v.y;
            As[kq + 2][m] = v.z; As[kq + 3][m] = v.w;
        }
        // load B tile (16 x 128)
        #pragma unroll
        for (int i = 0; i < 2; i++) {
            int idx = tid + i * 256;
            int kk  = idx >> 5;               // 0..15
            int n4  = (idx & 31) << 2;        // 0..124
            *(float4*)&Bs[kk][n4] =
                *(const float4*)(B + (size_t)(k0 + kk) * HID + n4);
        }
        __syncthreads();

        #pragma unroll
        for (int k = 0; k < 16; k++) {
            float a[8], b[8];
            *(float4*)&a[0] = *(const float4*)&As[k][cRow];
            *(float4*)&a[4] = *(const float4*)&As[k][cRow + 4];
            *(float4*)&b[0] = *(const float4*)&Bs[k][cCol];
            *(float4*)&b[4] = *(const float4*)&Bs[k][cCol + 4];
            #pragma unroll
            for (int i = 0; i < 8; i++)
                #pragma unroll
                for (int j = 0; j < 8; j++)
                    acc[i][j] = fmaf(a[i], b[j], acc[i][j]);
        }
        __syncthreads();
    }

    #pragma unroll
    for (int i = 0; i < 8; i++) {
        int gr = rowBase + cRow + i;
        if (gr >= Nrows) continue;
        float* cp = C + (size_t)gr * ldc + cCol;
        #pragma unroll
        for (int j4 = 0; j4 < 8; j4 += 4) {
            float4 v;
            v.x = acc[i][j4 + 0]; v.y = acc[i][j4 + 1];
            v.z = acc[i][j4 + 2]; v.w = acc[i][j4 + 3];
            if (bias) {
                v.x += bias[cCol + j4 + 0]; v.y += bias[cCol + j4 + 1];
                v.z += bias[cCol + j4 + 2]; v.w += bias[cCol + j4 + 3];
            }
            *(float4*)(cp + j4) = v;
        }
    }
}

// ---------------- edge scatter: out[tgt] += x'[src, et] * invc[tgt, et] -----------
// One warp per edge; lane handles 4 floats via red.global.add.v4.f32 (L2-resident dst).
__global__ __launch_bounds__(256) void scatter_edges_kernel(float* __restrict__ out)
{
    int wid  = (blockIdx.x * blockDim.x + threadIdx.x) >> 5;
    int lane = threadIdx.x & 31;
    if (wid >= N_EDGES) return;

    int so = g_srcOff[wid];
    if (so < 0) return;  // invalid edge (guarded in prep)
    float inv = g_invc[g_segid[wid]];
    float* dst = out + (size_t)g_tgt[wid] * HID + lane * 4;

    float4 v = *(const float4*)(g_xprime + (size_t)so + lane * 4);
    v.x *= inv; v.y *= inv; v.z *= inv; v.w *= inv;

    asm volatile("red.global.add.v4.f32 [%0], {%1,%2,%3,%4};"
                 :: "l"(dst), "f"(v.x), "f"(v.y), "f"(v.z), "f"(v.w)
                 : "memory");
}

// ---------------- launch ----------------
extern "C" void kernel_launch(void* const* d_in, const int* in_sizes, int n_in,
                              void* d_out, int out_size)
{
    const int*   edge_index = (const int*)d_in[0];
    const int*   edge_type  = (const int*)d_in[1];
    const float* node_init  = (const float*)d_in[2];
    const float* W          = (const float*)d_in[3];
    const float* root       = (const float*)d_in[4];
    const float* bias       = (const float*)d_in[5];
    float*       out        = (float*)d_out;

    void* p;
    cudaGetSymbolAddress(&p, g_xprime); float* xprime = (float*)p;
    cudaGetSymbolAddress(&p, g_bufA);   float* bufA   = (float*)p;
    cudaGetSymbolAddress(&p, g_bufB);   float* bufB   = (float*)p;

    // edge prep (once per launch, reused by all 3 layers)
    zero_cnt_kernel<<<(N_NODES * N_REL + 255) / 256, 256>>>();
    prep_edges_kernel<<<(N_EDGES + 255) / 256, 256>>>(edge_index, edge_type);
    make_invc_kernel<<<(N_NODES * N_REL + 255) / 256, 256>>>();

    const int rowTiles = (N_NODES + 127) / 128;
    const float* xin = node_init;

    for (int l = 0; l < N_LAYERS; l++) {
        float* xout = (l == N_LAYERS - 1) ? out : (l == 0 ? bufA : bufB);
        int relu = (l > 0) ? 1 : 0;

        // x' = act(x) @ W[l][r]  for all 16 relations (batched over grid.z)
        dim3 g1(rowTiles, 1, N_REL);
        sgemm_rgcn<<<g1, 256>>>(xin, W + (size_t)l * N_REL * HID * HID,
                                xprime, N_REL * HID, nullptr, relu, N_NODES);

        // out = act(x) @ root[l] + bias[l]
        dim3 g2(rowTiles, 1, 1);
        sgemm_rgcn<<<g2, 256>>>(xin, root + (size_t)l * HID * HID,
                                xout, HID, bias + (size_t)l * HID, relu, N_NODES);

        // out[tgt] += x'[src, et] * invc[tgt, et]
        int warpsPerBlock = 256 / 32;
        int blocks = (N_EDGES + warpsPerBlock - 1) / warpsPerBlock;
        scatter_edges_kernel<<<blocks, 256>>>(xout);
        xin = xout;
    }
}

// round 5
// speedup vs baseline: 1.5136x; 1.5136x over previous
#include <cuda_runtime.h>
#include <cuda_bf16.h>
#include <cstdint>

#define N_NODES  50000
#define N_REL    16
#define HID      128
#define N_LAYERS 3
#define N_EDGES  1600000

// ================= device scratch (no cudaMalloc allowed) =================
__device__ __align__(16) float g_xprime[(size_t)N_NODES * N_REL * HID]; // 409.6 MB
__device__ __align__(16) float g_bufA[(size_t)N_NODES * HID];
__device__ __align__(16) float g_bufB[(size_t)N_NODES * HID];
__device__ __align__(16) float g_invc[N_NODES * N_REL];
__device__ int g_cnt [N_NODES * N_REL];
__device__ int g_srcOff[N_EDGES];   // src*R*HID + et*HID, or -1 if invalid
__device__ int g_segid [N_EDGES];   // tgt*R + et
__device__ int g_tgt   [N_EDGES];
// W split to bf16 hi/lo, transposed to [n][k] row-major, 16384 elems/tile.
__device__ __align__(16) __nv_bfloat16 g_whi[(size_t)N_LAYERS * N_REL * 16384];
__device__ __align__(16) __nv_bfloat16 g_wlo[(size_t)N_LAYERS * N_REL * 16384];

// ================= helpers =================
__device__ __forceinline__ uint32_t smem_to_u32(const void* p) {
    uint32_t a;
    asm("{ .reg .u64 t; cvta.to.shared.u64 t, %1; cvt.u32.u64 %0, t; }"
        : "=r"(a) : "l"(p));
    return a;
}
__device__ __forceinline__ void ldsm_x4(uint32_t* r, uint32_t addr) {
    asm volatile("ldmatrix.sync.aligned.m8n8.x4.shared.b16 {%0,%1,%2,%3}, [%4];"
        : "=r"(r[0]), "=r"(r[1]), "=r"(r[2]), "=r"(r[3]) : "r"(addr));
}
__device__ __forceinline__ void mma_bf16(float* d, const uint32_t* a, const uint32_t* b) {
    asm volatile("mma.sync.aligned.m16n8k16.row.col.f32.bf16.bf16.f32 "
        "{%0,%1,%2,%3}, {%4,%5,%6,%7}, {%8,%9}, {%0,%1,%2,%3};"
        : "+f"(d[0]), "+f"(d[1]), "+f"(d[2]), "+f"(d[3])
        : "r"(a[0]), "r"(a[1]), "r"(a[2]), "r"(a[3]), "r"(b[0]), "r"(b[1]));
}

// ================= edge prep ==============================================
__global__ void zero_cnt_kernel() {
    int i = blockIdx.x * blockDim.x + threadIdx.x;
    if (i < N_NODES * N_REL) g_cnt[i] = 0;
}
__global__ void prep_edges_kernel(const int* __restrict__ edge_index,
                                  const int* __restrict__ edge_type) {
    int e = blockIdx.x * blockDim.x + threadIdx.x;
    if (e >= N_EDGES) return;
    int s = edge_index[e];
    int t = edge_index[N_EDGES + e];
    int r = edge_type[e];
    if ((unsigned)s >= N_NODES || (unsigned)t >= N_NODES || (unsigned)r >= N_REL) {
        g_srcOff[e] = -1; g_segid[e] = 0; g_tgt[e] = 0; return;
    }
    g_srcOff[e] = s * (N_REL * HID) + r * HID;
    g_segid[e]  = t * N_REL + r;
    g_tgt[e]    = t;
    atomicAdd(&g_cnt[t * N_REL + r], 1);
}
__global__ void make_invc_kernel() {
    int i = blockIdx.x * blockDim.x + threadIdx.x;
    if (i < N_NODES * N_REL) {
        int c = g_cnt[i];
        g_invc[i] = 1.0f / (float)(c > 0 ? c : 1);
    }
}

// W[l][r][k][n] fp32 -> [n][k] row-major, split bf16 hi/lo.
__global__ void conv_w_kernel(const float* __restrict__ W) {
    int t = blockIdx.x * blockDim.x + threadIdx.x;
    if (t >= N_LAYERS * N_REL * HID * HID) return;
    int lr  = t >> 14;            // tile index (l*16+r)
    int rem = t & 16383;
    int n = rem >> 7;
    int k = rem & 127;
    float v = W[((size_t)lr * HID + k) * HID + n];
    __nv_bfloat16 hi = __float2bfloat16(v);
    __nv_bfloat16 lo = __float2bfloat16(v - __bfloat162float(hi));
    size_t off = (size_t)lr * 16384 + n * HID + k;
    g_whi[off] = hi;
    g_wlo[off] = lo;
}

// ================= relation GEMM via mma.sync (bf16 split) ================
// smem tiles padded to 136 bf16/row (272B) -> conflict-free ldmatrix.
#define TPAD      136
#define TILE_B    (128 * TPAD * 2)           // 34816 bytes per tile
#define SM_AHI    0
#define SM_ALO    (SM_AHI + TILE_B)
#define SM_BHI    (SM_ALO + TILE_B)
#define SM_BLO    (SM_BHI + TILE_B)
#define SM_TOTAL  (SM_BLO + TILE_B)          // 139264

__global__ __launch_bounds__(256) void rgcn_rel_mma(
    const float* __restrict__ xin,
    const __nv_bfloat16* __restrict__ whi,
    const __nv_bfloat16* __restrict__ wlo,
    float* __restrict__ xprime, int relu)
{
    extern __shared__ __align__(16) char smem[];
    const uint32_t sb = smem_to_u32(smem);
    const int tid  = threadIdx.x;
    const int wid  = tid >> 5;
    const int lane = tid & 31;
    const int rowBase = blockIdx.x * 128;

    // ---- A tile: load fp32, relu, split into hi/lo bf16 (padded layout) ----
    #pragma unroll
    for (int i = 0; i < 16; i++) {
        int idx4 = tid + i * 256;            // 0..4095 (float4 index)
        int m  = idx4 >> 5;
        int kq = (idx4 & 31) << 2;
        int gr = rowBase + m;
        float4 v = make_float4(0.f, 0.f, 0.f, 0.f);
        if (gr < N_NODES) v = *(const float4*)(xin + (size_t)gr * HID + kq);
        if (relu) { v.x = fmaxf(v.x, 0.f); v.y = fmaxf(v.y, 0.f);
                    v.z = fmaxf(v.z, 0.f); v.w = fmaxf(v.w, 0.f); }
        __nv_bfloat16 h0 = __float2bfloat16(v.x), h1 = __float2bfloat16(v.y);
        __nv_bfloat16 h2 = __float2bfloat16(v.z), h3 = __float2bfloat16(v.w);
        __nv_bfloat16 l0 = __float2bfloat16(v.x - __bfloat162float(h0));
        __nv_bfloat16 l1 = __float2bfloat16(v.y - __bfloat162float(h1));
        __nv_bfloat16 l2 = __float2bfloat16(v.z - __bfloat162float(h2));
        __nv_bfloat16 l3 = __float2bfloat16(v.w - __bfloat162float(h3));
        uint32_t boff = (uint32_t)m * (TPAD * 2) + kq * 2;
        __nv_bfloat162* ph = (__nv_bfloat162*)(smem + SM_AHI + boff);
        __nv_bfloat162* pl = (__nv_bfloat162*)(smem + SM_ALO + boff);
        ph[0] = __nv_bfloat162(h0, h1); ph[1] = __nv_bfloat162(h2, h3);
        pl[0] = __nv_bfloat162(l0, l1); pl[1] = __nv_bfloat162(l2, l3);
    }

    const int mW = (wid & 3) * 32;           // warp row offset within tile
    const int nW = (wid >> 2) * 64;          // warp col offset

    for (int z = 0; z < N_REL; z++) {
        __syncthreads();  // prior relation's ldmatrix reads of B done
        // ---- copy B hi/lo (32KB each) into padded smem layout ----
        {
            const float4* sh = (const float4*)(whi + (size_t)z * 16384);
            const float4* sl = (const float4*)(wlo + (size_t)z * 16384);
            #pragma unroll
            for (int i = 0; i < 8; i++) {
                int c = tid + i * 256;       // 0..2047 chunks of 16B
                int row = c >> 4, c16 = c & 15;
                uint32_t doff = (uint32_t)row * (TPAD * 2) + c16 * 16;
                *(float4*)(smem + SM_BHI + doff) = sh[c];
                *(float4*)(smem + SM_BLO + doff) = sl[c];
            }
        }
        __syncthreads();

        float acc[2][8][4];
        #pragma unroll
        for (int mt = 0; mt < 2; mt++)
            #pragma unroll
            for (int nt = 0; nt < 8; nt++)
                #pragma unroll
                for (int q = 0; q < 4; q++) acc[mt][nt][q] = 0.0f;

        #pragma unroll
        for (int term = 0; term < 3; term++) {
            const uint32_t aBase = sb + (term == 2 ? SM_ALO : SM_AHI);
            const uint32_t bBase = sb + (term == 1 ? SM_BLO : SM_BHI);
            #pragma unroll
            for (int k0 = 0; k0 < HID; k0 += 16) {
                uint32_t a[2][4];
                {
                    int ar = mW + (lane & 15);
                    int ac = k0 + ((lane >> 4) << 3);
                    ldsm_x4(a[0], aBase + (uint32_t)ar * (TPAD * 2) + ac * 2);
                    ldsm_x4(a[1], aBase + (uint32_t)(ar + 16) * (TPAD * 2) + ac * 2);
                }
                uint32_t b[8][2];
                #pragma unroll
                for (int p = 0; p < 4; p++) {
                    int g  = lane >> 3;
                    int nn = nW + p * 16 + (lane & 7) + ((g >> 1) << 3);
                    int kk = k0 + ((g & 1) << 3);
                    uint32_t r[4];
                    ldsm_x4(r, bBase + (uint32_t)nn * (TPAD * 2) + kk * 2);
                    b[p*2][0] = r[0]; b[p*2][1] = r[1];
                    b[p*2+1][0] = r[2]; b[p*2+1][1] = r[3];
                }
                #pragma unroll
                for (int mt = 0; mt < 2; mt++)
                    #pragma unroll
                    for (int nt = 0; nt < 8; nt++)
                        mma_bf16(acc[mt][nt], a[mt], b[nt]);
            }
        }

        // ---- epilogue: write D to xprime[row][z*128 + col] ----
        #pragma unroll
        for (int mt = 0; mt < 2; mt++) {
            int r0 = rowBase + mW + mt * 16 + (lane >> 2);
            int r1 = r0 + 8;
            #pragma unroll
            for (int nt = 0; nt < 8; nt++) {
                int col = nW + nt * 8 + (lane & 3) * 2;
                if (r0 < N_NODES)
                    *(float2*)(xprime + ((size_t)r0 * N_REL + z) * HID + col) =
                        make_float2(acc[mt][nt][0], acc[mt][nt][1]);
                if (r1 < N_NODES)
                    *(float2*)(xprime + ((size_t)r1 * N_REL + z) * HID + col) =
                        make_float2(acc[mt][nt][2], acc[mt][nt][3]);
            }
        }
    }
}

// ================= root GEMM (fp32 SIMT, small) ===========================
__global__ __launch_bounds__(256) void sgemm_root(
    const float* __restrict__ A, const float* __restrict__ B,
    float* __restrict__ C, const float* __restrict__ bias, int relu)
{
    __shared__ __align__(16) float As[16][128];
    __shared__ __align__(16) float Bs[16][128];
    const int tid = threadIdx.x;
    const int rowBase = blockIdx.x * 128;
    const int tx = tid & 15, ty = tid >> 4;
    const int cRow = ty * 8, cCol = tx * 8;

    float acc[8][8];
    #pragma unroll
    for (int i = 0; i < 8; i++)
        #pragma unroll
        for (int j = 0; j < 8; j++) acc[i][j] = 0.0f;

    for (int k0 = 0; k0 < HID; k0 += 16) {
        #pragma unroll
        for (int i = 0; i < 2; i++) {
            int idx = tid + i * 256;
            int m = idx >> 2, kq = (idx & 3) << 2;
            int gr = rowBase + m;
            float4 v = make_float4(0.f, 0.f, 0.f, 0.f);
            if (gr < N_NODES) v = *(const float4*)(A + (size_t)gr * HID + k0 + kq);
            if (relu) { v.x = fmaxf(v.x, 0.f); v.y = fmaxf(v.y, 0.f);
                        v.z = fmaxf(v.z, 0.f); v.w = fmaxf(v.w, 0.f); }
            As[kq+0][m] = v.x; As[kq+1][m] = v.y; As[kq+2][m] = v.z; As[kq+3][m] = v.w;
        }
        #pragma unroll
        for (int i = 0; i < 2; i++) {
            int idx = tid + i * 256;
            int kk = idx >> 5, n4 = (idx & 31) << 2;
            *(float4*)&Bs[kk][n4] = *(const float4*)(B + (size_t)(k0 + kk) * HID + n4);
        }
        __syncthreads();
        #pragma unroll
        for (int k = 0; k < 16; k++) {
            float a[8], b[8];
            *(float4*)&a[0] = *(const float4*)&As[k][cRow];
            *(float4*)&a[4] = *(const float4*)&As[k][cRow + 4];
            *(float4*)&b[0] = *(const float4*)&Bs[k][cCol];
            *(float4*)&b[4] = *(const float4*)&Bs[k][cCol + 4];
            #pragma unroll
            for (int i = 0; i < 8; i++)
                #pragma unroll
                for (int j = 0; j < 8; j++)
                    acc[i][j] = fmaf(a[i], b[j], acc[i][j]);
        }
        __syncthreads();
    }
    #pragma unroll
    for (int i = 0; i < 8; i++) {
        int gr = rowBase + cRow + i;
        if (gr >= N_NODES) continue;
        float* cp = C + (size_t)gr * HID + cCol;
        #pragma unroll
        for (int j4 = 0; j4 < 8; j4 += 4) {
            float4 v = make_float4(acc[i][j4+0] + bias[cCol+j4+0],
                                   acc[i][j4+1] + bias[cCol+j4+1],
                                   acc[i][j4+2] + bias[cCol+j4+2],
                                   acc[i][j4+3] + bias[cCol+j4+3]);
            *(float4*)(cp + j4) = v;
        }
    }
}

// ================= edge scatter ===========================================
__global__ __launch_bounds__(256) void scatter_edges_kernel(float* __restrict__ out)
{
    int wid  = (blockIdx.x * blockDim.x + threadIdx.x) >> 5;
    int lane = threadIdx.x & 31;
    if (wid >= N_EDGES) return;
    int so = g_srcOff[wid];
    if (so < 0) return;
    float inv = g_invc[g_segid[wid]];
    float* dst = out + (size_t)g_tgt[wid] * HID + lane * 4;
    float4 v = *(const float4*)(g_xprime + (size_t)so + lane * 4);
    v.x *= inv; v.y *= inv; v.z *= inv; v.w *= inv;
    asm volatile("red.global.add.v4.f32 [%0], {%1,%2,%3,%4};"
                 :: "l"(dst), "f"(v.x), "f"(v.y), "f"(v.z), "f"(v.w) : "memory");
}

// ================= launch ================================================
extern "C" void kernel_launch(void* const* d_in, const int* in_sizes, int n_in,
                              void* d_out, int out_size)
{
    const int*   edge_index = (const int*)d_in[0];
    const int*   edge_type  = (const int*)d_in[1];
    const float* node_init  = (const float*)d_in[2];
    const float* W          = (const float*)d_in[3];
    const float* root       = (const float*)d_in[4];
    const float* bias       = (const float*)d_in[5];
    float*       out        = (float*)d_out;

    void* p;
    cudaGetSymbolAddress(&p, g_xprime); float* xprime = (float*)p;
    cudaGetSymbolAddress(&p, g_bufA);   float* bufA   = (float*)p;
    cudaGetSymbolAddress(&p, g_bufB);   float* bufB   = (float*)p;
    cudaGetSymbolAddress(&p, g_whi);    __nv_bfloat16* whi = (__nv_bfloat16*)p;
    cudaGetSymbolAddress(&p, g_wlo);    __nv_bfloat16* wlo = (__nv_bfloat16*)p;

    cudaFuncSetAttribute(rgcn_rel_mma, cudaFuncAttributeMaxDynamicSharedMemorySize, SM_TOTAL);

    // one-time prep
    zero_cnt_kernel<<<(N_NODES * N_REL + 255) / 256, 256>>>();
    prep_edges_kernel<<<(N_EDGES + 255) / 256, 256>>>(edge_index, edge_type);
    make_invc_kernel<<<(N_NODES * N_REL + 255) / 256, 256>>>();
    conv_w_kernel<<<(N_LAYERS * N_REL * HID * HID + 255) / 256, 256>>>(W);

    const int rowTiles = (N_NODES + 127) / 128;
    const float* xin = node_init;

    for (int l = 0; l < N_LAYERS; l++) {
        float* xout = (l == N_LAYERS - 1) ? out : (l == 0 ? bufA : bufB);
        int relu = (l > 0) ? 1 : 0;

        rgcn_rel_mma<<<rowTiles, 256, SM_TOTAL>>>(
            xin, whi + (size_t)l * N_REL * 16384, wlo + (size_t)l * N_REL * 16384,
            xprime, relu);

        sgemm_root<<<rowTiles, 256>>>(xin, root + (size_t)l * HID * HID,
                                      xout, bias + (size_t)l * HID, relu);

        int blocks = (N_EDGES + 7) / 8;
        scatter_edges_kernel<<<blocks, 256>>>(xout);
        xin = xout;
    }
}

// round 6
// speedup vs baseline: 1.7375x; 1.1479x over previous
#include <cuda_runtime.h>
#include <cuda_bf16.h>
#include <cstdint>

#define N_NODES  50000
#define N_REL    16
#define HID      128
#define N_LAYERS 3
#define N_EDGES  1600000
#define NSEG     (N_NODES * N_REL)   // 800000
#define KTOT     (N_REL * HID)       // 2048
#define NCHUNK   (N_REL + 1)         // 16 relations + root

// ================= device scratch (no cudaMalloc allowed) =================
__device__ __align__(16) __nv_bfloat16 g_agghi[(size_t)N_NODES * KTOT]; // 204.8 MB
__device__ __align__(16) __nv_bfloat16 g_agglo[(size_t)N_NODES * KTOT]; // 204.8 MB
__device__ __align__(16) float g_bufA[(size_t)N_NODES * HID];
__device__ __align__(16) float g_bufB[(size_t)N_NODES * HID];
// weight stack: per layer 17 tiles of [n][k] bf16 (16 relations + root)
__device__ __align__(16) __nv_bfloat16 g_whi[(size_t)N_LAYERS * NCHUNK * 16384];
__device__ __align__(16) __nv_bfloat16 g_wlo[(size_t)N_LAYERS * NCHUNK * 16384];
__device__ int g_cnt[NSEG];
__device__ int g_segstart[NSEG];
__device__ int g_cursor[NSEG];
__device__ int g_blksum[1024];
__device__ int g_blkoff[1024];
__device__ int g_eseg[N_EDGES];
__device__ int g_esrc[N_EDGES];
__device__ int g_srcSorted[N_EDGES];

// ================= helpers =================
__device__ __forceinline__ uint32_t smem_to_u32(const void* p) {
    uint32_t a;
    asm("{ .reg .u64 t; cvta.to.shared.u64 t, %1; cvt.u32.u64 %0, t; }"
        : "=r"(a) : "l"(p));
    return a;
}
__device__ __forceinline__ void ldsm_x4(uint32_t* r, uint32_t addr) {
    asm volatile("ldmatrix.sync.aligned.m8n8.x4.shared.b16 {%0,%1,%2,%3}, [%4];"
        : "=r"(r[0]), "=r"(r[1]), "=r"(r[2]), "=r"(r[3]) : "r"(addr));
}
__device__ __forceinline__ void mma_bf16(float* d, const uint32_t* a, const uint32_t* b) {
    asm volatile("mma.sync.aligned.m16n8k16.row.col.f32.bf16.bf16.f32 "
        "{%0,%1,%2,%3}, {%4,%5,%6,%7}, {%8,%9}, {%0,%1,%2,%3};"
        : "+f"(d[0]), "+f"(d[1]), "+f"(d[2]), "+f"(d[3])
        : "r"(a[0]), "r"(a[1]), "r"(a[2]), "r"(a[3]), "r"(b[0]), "r"(b[1]));
}

// ================= edge prep ==============================================
__global__ void zero_cnt_kernel() {
    int i = blockIdx.x * blockDim.x + threadIdx.x;
    if (i < NSEG) g_cnt[i] = 0;
}
__global__ void prep_edges_kernel(const int* __restrict__ edge_index,
                                  const int* __restrict__ edge_type) {
    int e = blockIdx.x * blockDim.x + threadIdx.x;
    if (e >= N_EDGES) return;
    int s = edge_index[e];
    int t = edge_index[N_EDGES + e];
    int r = edge_type[e];
    if ((unsigned)s >= N_NODES || (unsigned)t >= N_NODES || (unsigned)r >= N_REL) {
        g_eseg[e] = -1; g_esrc[e] = 0; return;
    }
    g_eseg[e] = t * N_REL + r;
    g_esrc[e] = s;
    atomicAdd(&g_cnt[t * N_REL + r], 1);
}

// ---- counting-sort scan: segstart = exclusive_scan(cnt) ----
__global__ void scan1_kernel() {   // 782 blocks x 256 thr x 4 elems
    __shared__ int s[256];
    int base = blockIdx.x * 1024;
    int t = threadIdx.x;
    int v[4]; int sum = 0;
    #pragma unroll
    for (int j = 0; j < 4; j++) {
        int idx = base + t * 4 + j;
        v[j] = (idx < NSEG) ? g_cnt[idx] : 0;
        sum += v[j];
    }
    s[t] = sum; __syncthreads();
    for (int off = 1; off < 256; off <<= 1) {
        int x = 0;
        if (t >= off) x = s[t - off];
        __syncthreads();
        if (t >= off) s[t] += x;
        __syncthreads();
    }
    int excl = (t > 0) ? s[t - 1] : 0;
    if (t == 255) g_blksum[blockIdx.x] = s[255];
    int run = excl;
    #pragma unroll
    for (int j = 0; j < 4; j++) {
        int idx = base + t * 4 + j;
        if (idx < NSEG) g_segstart[idx] = run;
        run += v[j];
    }
}
__global__ void scan2_kernel(int nb) {   // 1 block
    __shared__ int s[256];
    int t = threadIdx.x;
    int v[4]; int sum = 0;
    #pragma unroll
    for (int j = 0; j < 4; j++) {
        int idx = t * 4 + j;
        v[j] = (idx < nb) ? g_blksum[idx] : 0;
        sum += v[j];
    }
    s[t] = sum; __syncthreads();
    for (int off = 1; off < 256; off <<= 1) {
        int x = 0;
        if (t >= off) x = s[t - off];
        __syncthreads();
        if (t >= off) s[t] += x;
        __syncthreads();
    }
    int excl = (t > 0) ? s[t - 1] : 0;
    int run = excl;
    #pragma unroll
    for (int j = 0; j < 4; j++) {
        int idx = t * 4 + j;
        if (idx < nb) g_blkoff[idx] = run;
        run += v[j];
    }
}
__global__ void scan3_kernel() {
    int i = blockIdx.x * blockDim.x + threadIdx.x;
    if (i >= NSEG) return;
    int v = g_segstart[i] + g_blkoff[i >> 10];
    g_segstart[i] = v;
    g_cursor[i] = v;
}
__global__ void bin_edges_kernel() {
    int e = blockIdx.x * blockDim.x + threadIdx.x;
    if (e >= N_EDGES) return;
    int seg = g_eseg[e];
    if (seg < 0) return;
    int pos = atomicAdd(&g_cursor[seg], 1);
    g_srcSorted[pos] = g_esrc[e];
}

// W[l][r][k][n] & root[l][k][n] fp32 -> stacked [n][k] bf16 hi/lo tiles.
__global__ void conv_w_kernel(const float* __restrict__ W,
                              const float* __restrict__ root) {
    int t = blockIdx.x * blockDim.x + threadIdx.x;
    if (t >= N_LAYERS * NCHUNK * 16384) return;
    int tt  = t >> 14;            // tile 0..50
    int rem = t & 16383;
    int n = rem >> 7;
    int k = rem & 127;
    int l = tt / NCHUNK;
    int c = tt % NCHUNK;
    float v;
    if (c < N_REL) v = W[(((size_t)l * N_REL + c) * HID + k) * HID + n];
    else           v = root[((size_t)l * HID + k) * HID + n];
    __nv_bfloat16 hi = __float2bfloat16(v);
    __nv_bfloat16 lo = __float2bfloat16(v - __bfloat162float(hi));
    size_t off = (size_t)tt * 16384 + n * HID + k;
    g_whi[off] = hi;
    g_wlo[off] = lo;
}

// ================= per-layer aggregation (no atomics) =====================
// One warp per (node,rel) segment: mean of x[src] rows over sorted edges,
// split to bf16 hi/lo, streamed out (evict-first).
__global__ __launch_bounds__(256) void agg_kernel(const float* __restrict__ x,
                                                  int relu)
{
    int w = (blockIdx.x * 256 + threadIdx.x) >> 5;
    int lane = threadIdx.x & 31;
    if (w >= NSEG) return;
    int start = g_segstart[w];
    int c = g_cnt[w];
    float4 sum = make_float4(0.f, 0.f, 0.f, 0.f);
    for (int i = 0; i < c; i++) {
        int s = g_srcSorted[start + i];
        float4 v = *(const float4*)(x + (size_t)s * HID + lane * 4);
        if (relu) { v.x = fmaxf(v.x, 0.f); v.y = fmaxf(v.y, 0.f);
                    v.z = fmaxf(v.z, 0.f); v.w = fmaxf(v.w, 0.f); }
        sum.x += v.x; sum.y += v.y; sum.z += v.z; sum.w += v.w;
    }
    float inv = (c > 0) ? 1.0f / (float)c : 0.0f;
    sum.x *= inv; sum.y *= inv; sum.z *= inv; sum.w *= inv;

    __nv_bfloat16 h0 = __float2bfloat16(sum.x), h1 = __float2bfloat16(sum.y);
    __nv_bfloat16 h2 = __float2bfloat16(sum.z), h3 = __float2bfloat16(sum.w);
    __nv_bfloat16 l0 = __float2bfloat16(sum.x - __bfloat162float(h0));
    __nv_bfloat16 l1 = __float2bfloat16(sum.y - __bfloat162float(h1));
    __nv_bfloat16 l2 = __float2bfloat16(sum.z - __bfloat162float(h2));
    __nv_bfloat16 l3 = __float2bfloat16(sum.w - __bfloat162float(h3));
    __nv_bfloat162 H0(h0, h1), H1(h2, h3), L0(l0, l1), L1(l2, l3);
    size_t off = (size_t)w * HID + lane * 4;
    asm volatile("st.global.cs.v2.b32 [%0], {%1,%2};"
                 :: "l"(g_agghi + off), "r"(*(uint32_t*)&H0), "r"(*(uint32_t*)&H1) : "memory");
    asm volatile("st.global.cs.v2.b32 [%0], {%1,%2};"
                 :: "l"(g_agglo + off), "r"(*(uint32_t*)&L0), "r"(*(uint32_t*)&L1) : "memory");
}

// ================= fused layer GEMM: out = [agg | x] @ [Wstk; root] + bias =
// K = 17 chunks x 128. mma.sync bf16 3-term split, padded smem (TPAD).
#define TPAD      136
#define TILE_B    (128 * TPAD * 2)           // 34816 bytes
#define SM_AHI    0
#define SM_ALO    (SM_AHI + TILE_B)
#define SM_BHI    (SM_ALO + TILE_B)
#define SM_BLO    (SM_BHI + TILE_B)
#define SM_TOTAL  (SM_BLO + TILE_B)          // 139264

__global__ __launch_bounds__(256) void rgcn_gemm(
    const float* __restrict__ xin,
    const __nv_bfloat16* __restrict__ whi,   // layer's 17-tile stack
    const __nv_bfloat16* __restrict__ wlo,
    const float* __restrict__ bias,
    float* __restrict__ out, int relu)
{
    extern __shared__ __align__(16) char smem[];
    const uint32_t sb = smem_to_u32(smem);
    const int tid  = threadIdx.x;
    const int wid  = tid >> 5;
    const int lane = tid & 31;
    const int rowBase = blockIdx.x * 128;

    const int mW = (wid & 3) * 32;
    const int nW = (wid >> 2) * 64;

    float acc[2][8][4];
    #pragma unroll
    for (int mt = 0; mt < 2; mt++)
        #pragma unroll
        for (int nt = 0; nt < 8; nt++)
            #pragma unroll
            for (int q = 0; q < 4; q++) acc[mt][nt][q] = 0.0f;

    for (int kc = 0; kc < NCHUNK; kc++) {
        __syncthreads();   // previous chunk's ldmatrix reads complete
        // ---- A chunk ----
        if (kc < N_REL) {
            // bf16 agg chunk: 128 rows x 256B per array (8 float4/thread)
            #pragma unroll
            for (int i = 0; i < 8; i++) {
                int idx4 = tid + i * 256;        // 0..2047
                int row = idx4 >> 4, c16 = idx4 & 15;
                int gr = rowBase + row;
                float4 vh = make_float4(0.f,0.f,0.f,0.f), vl = vh;
                if (gr < N_NODES) {
                    size_t o = (size_t)gr * KTOT + kc * HID + c16 * 8;
                    vh = *(const float4*)(g_agghi + o);
                    vl = *(const float4*)(g_agglo + o);
                }
                *(float4*)(smem + SM_AHI + row * (TPAD*2) + c16 * 16) = vh;
                *(float4*)(smem + SM_ALO + row * (TPAD*2) + c16 * 16) = vl;
            }
        } else {
            // root chunk: fp32 x + relu + split (16 float4/thread)
            #pragma unroll
            for (int i = 0; i < 16; i++) {
                int idx4 = tid + i * 256;        // 0..4095
                int row = idx4 >> 5, kq = (idx4 & 31) << 2;
                int gr = rowBase + row;
                float4 v = make_float4(0.f,0.f,0.f,0.f);
                if (gr < N_NODES) v = *(const float4*)(xin + (size_t)gr * HID + kq);
                if (relu) { v.x = fmaxf(v.x,0.f); v.y = fmaxf(v.y,0.f);
                            v.z = fmaxf(v.z,0.f); v.w = fmaxf(v.w,0.f); }
                __nv_bfloat16 h0 = __float2bfloat16(v.x), h1 = __float2bfloat16(v.y);
                __nv_bfloat16 h2 = __float2bfloat16(v.z), h3 = __float2bfloat16(v.w);
                __nv_bfloat16 l0 = __float2bfloat16(v.x - __bfloat162float(h0));
                __nv_bfloat16 l1 = __float2bfloat16(v.y - __bfloat162float(h1));
                __nv_bfloat16 l2 = __float2bfloat16(v.z - __bfloat162float(h2));
                __nv_bfloat16 l3 = __float2bfloat16(v.w - __bfloat162float(h3));
                uint32_t boff = (uint32_t)row * (TPAD*2) + kq * 2;
                __nv_bfloat162* ph = (__nv_bfloat162*)(smem + SM_AHI + boff);
                __nv_bfloat162* pl = (__nv_bfloat162*)(smem + SM_ALO + boff);
                ph[0] = __nv_bfloat162(h0, h1); ph[1] = __nv_bfloat162(h2, h3);
                pl[0] = __nv_bfloat162(l0, l1); pl[1] = __nv_bfloat162(l2, l3);
            }
        }
        // ---- B chunk (L2-resident weight stack) ----
        {
            const __nv_bfloat16* bh = whi + (size_t)kc * 16384;
            const __nv_bfloat16* bl = wlo + (size_t)kc * 16384;
            #pragma unroll
            for (int i = 0; i < 8; i++) {
                int idx4 = tid + i * 256;
                int row = idx4 >> 4, c16 = idx4 & 15;
                *(float4*)(smem + SM_BHI + row * (TPAD*2) + c16 * 16) =
                    *(const float4*)(bh + row * HID + c16 * 8);
                *(float4*)(smem + SM_BLO + row * (TPAD*2) + c16 * 16) =
                    *(const float4*)(bl + row * HID + c16 * 8);
            }
        }
        __syncthreads();

        // ---- MMA: 3 split terms over this 128-K chunk ----
        #pragma unroll
        for (int term = 0; term < 3; term++) {
            const uint32_t aBase = sb + (term == 2 ? SM_ALO : SM_AHI);
            const uint32_t bBase = sb + (term == 1 ? SM_BLO : SM_BHI);
            #pragma unroll
            for (int k0 = 0; k0 < HID; k0 += 16) {
                uint32_t a[2][4];
                {
                    int ar = mW + (lane & 15);
                    int ac = k0 + ((lane >> 4) << 3);
                    ldsm_x4(a[0], aBase + (uint32_t)ar * (TPAD*2) + ac * 2);
                    ldsm_x4(a[1], aBase + (uint32_t)(ar + 16) * (TPAD*2) + ac * 2);
                }
                uint32_t b[8][2];
                #pragma unroll
                for (int p = 0; p < 4; p++) {
                    int g  = lane >> 3;
                    int nn = nW + p * 16 + (lane & 7) + ((g >> 1) << 3);
                    int kk = k0 + ((g & 1) << 3);
                    uint32_t r[4];
                    ldsm_x4(r, bBase + (uint32_t)nn * (TPAD*2) + kk * 2);
                    b[p*2][0] = r[0]; b[p*2][1] = r[1];
                    b[p*2+1][0] = r[2]; b[p*2+1][1] = r[3];
                }
                #pragma unroll
                for (int mt = 0; mt < 2; mt++)
                    #pragma unroll
                    for (int nt = 0; nt < 8; nt++)
                        mma_bf16(acc[mt][nt], a[mt], b[nt]);
            }
        }
    }

    // ---- epilogue: + bias, direct store ----
    #pragma unroll
    for (int mt = 0; mt < 2; mt++) {
        int r0 = rowBase + mW + mt * 16 + (lane >> 2);
        int r1 = r0 + 8;
        #pragma unroll
        for (int nt = 0; nt < 8; nt++) {
            int col = nW + nt * 8 + (lane & 3) * 2;
            float b0 = bias[col], b1 = bias[col + 1];
            if (r0 < N_NODES)
                *(float2*)(out + (size_t)r0 * HID + col) =
                    make_float2(acc[mt][nt][0] + b0, acc[mt][nt][1] + b1);
            if (r1 < N_NODES)
                *(float2*)(out + (size_t)r1 * HID + col) =
                    make_float2(acc[mt][nt][2] + b0, acc[mt][nt][3] + b1);
        }
    }
}

// ================= launch ================================================
extern "C" void kernel_launch(void* const* d_in, const int* in_sizes, int n_in,
                              void* d_out, int out_size)
{
    const int*   edge_index = (const int*)d_in[0];
    const int*   edge_type  = (const int*)d_in[1];
    const float* node_init  = (const float*)d_in[2];
    const float* W          = (const float*)d_in[3];
    const float* root       = (const float*)d_in[4];
    const float* bias       = (const float*)d_in[5];
    float*       out        = (float*)d_out;

    void* p;
    cudaGetSymbolAddress(&p, g_bufA); float* bufA = (float*)p;
    cudaGetSymbolAddress(&p, g_bufB); float* bufB = (float*)p;
    cudaGetSymbolAddress(&p, g_whi);  __nv_bfloat16* whi = (__nv_bfloat16*)p;
    cudaGetSymbolAddress(&p, g_wlo);  __nv_bfloat16* wlo = (__nv_bfloat16*)p;

    cudaFuncSetAttribute(rgcn_gemm, cudaFuncAttributeMaxDynamicSharedMemorySize, SM_TOTAL);

    // one-time prep: histogram + scan + counting-sort + weight conversion
    const int scanBlocks = (NSEG + 1023) / 1024;   // 782
    zero_cnt_kernel<<<(NSEG + 255) / 256, 256>>>();
    prep_edges_kernel<<<(N_EDGES + 255) / 256, 256>>>(edge_index, edge_type);
    scan1_kernel<<<scanBlocks, 256>>>();
    scan2_kernel<<<1, 256>>>(scanBlocks);
    scan3_kernel<<<(NSEG + 255) / 256, 256>>>();
    bin_edges_kernel<<<(N_EDGES + 255) / 256, 256>>>();
    conv_w_kernel<<<(N_LAYERS * NCHUNK * 16384 + 255) / 256, 256>>>(W, root);

    const int rowTiles = (N_NODES + 127) / 128;    // 391
    const float* xin = node_init;

    for (int l = 0; l < N_LAYERS; l++) {
        float* xout = (l == N_LAYERS - 1) ? out : (l == 0 ? bufA : bufB);
        int relu = (l > 0) ? 1 : 0;

        agg_kernel<<<NSEG / 8, 256>>>(xin, relu);
        rgcn_gemm<<<rowTiles, 256, SM_TOTAL>>>(
            xin, whi + (size_t)l * NCHUNK * 16384, wlo + (size_t)l * NCHUNK * 16384,
            bias + (size_t)l * HID, xout, relu);
        xin = xout;
    }
}